// round 15
// baseline (speedup 1.0000x reference)
#include <cuda_runtime.h>
#include <cuda_fp16.h>
#include <stdint.h>

#define NN 50000
#define EE 320000
#define FF 256
#define KK 2
#define KDIM 512
#define KITERS 16        // KDIM / 32 (BK = 32 halves)

// Scratch (allocation-free rule: __device__ globals). fp16 packed as half2 words.
// g_degi zero at load; scan re-zeroes after reading so graph replays see zeros.
// g_done zero at load; last deg block resets it each call.
__device__ unsigned g_xph[(size_t)NN * FF / 2];      // half2(A_hat @ x)
__device__ unsigned g_xh[(size_t)NN * FF / 2];       // half2(x)
__device__ unsigned g_wh[2][KK][FF][FF / 2];         // half2 W^T, k-permuted per 8-word group
__device__ int   g_degi[NN];
__device__ float g_dinv[NN];
__device__ int   g_rowstart[NN + 1];
__device__ int   g_cursor[NN];
__device__ int   g_csr_src[EE];
__device__ float g_csr_w[EE];
__device__ int   g_done;

__device__ __forceinline__ unsigned pack_h2(float a, float b) {
    __half2 h = __floats2half2_rn(a, b);
    return *(unsigned*)&h;
}
__device__ __forceinline__ float2 h2f2(unsigned u) {
    return __half22float2(*(__half2*)&u);
}

// Per-block dtype sniff: int64 edge_index (ids < 2^31) => all odd 32-bit words 0.
// Requires blockDim.x == 256.
__device__ __forceinline__ int block_is64(const int* __restrict__ ei32) {
    __shared__ int s_any;
    if (threadIdx.x == 0) s_any = 0;
    __syncthreads();
    int v = ei32[2 * threadIdx.x + 1];
    v = __reduce_or_sync(0xffffffffu, v);
    if ((threadIdx.x & 31) == 0 && v) atomicOr(&s_any, 1);
    __syncthreads();
    return s_any == 0;
}

__device__ __forceinline__ int load_idx2(const void* ei, int which, int e, int is64) {
    if (is64) return (int)((const long long*)ei)[(size_t)which * EE + e];
    return ((const int*)ei)[(size_t)which * EE + e];
}

// ---------------------------------------------------------------------------
// 1) deg + cvt_x + cvt_w fused; LAST deg block also performs the scan
//    (overlapping the cvt streaming tail on other SMs).
// ---------------------------------------------------------------------------
#define DEG_BLOCKS ((EE + 255) / 256)             // 1250
#define CVTX_GROUPS (NN * FF / 8)                 // 1,600,000
#define CVTX_BLOCKS ((CVTX_GROUPS + 255) / 256)   // 6250
#define CVTW_THREADS (2 * KK * FF * (FF / 16))    // 16384
#define CVTW_BLOCKS (CVTW_THREADS / 256)          // 64
#define SCAN_CH2 196                              // 256 * 196 = 50176 >= NN

__device__ __forceinline__ void scan_256() {
    // Two-pass exclusive scan over g_degi (L2-hot, 200 KB), 256 threads.
    __shared__ int s[256];
    const int t = threadIdx.x;
    const int base = t * SCAN_CH2;

    int sum = 0;
    for (int i = 0; i < SCAN_CH2; ++i) {
        int idx = base + i;
        if (idx < NN) sum += g_degi[idx];
    }
    s[t] = sum;
    __syncthreads();
    for (int off = 1; off < 256; off <<= 1) {
        int v = (t >= off) ? s[t - off] : 0;
        __syncthreads();
        s[t] += v;
        __syncthreads();
    }
    int run = (t == 0) ? 0 : s[t - 1];
    for (int i = 0; i < SCAN_CH2; ++i) {
        int idx = base + i;
        if (idx < NN) {
            int d = g_degi[idx];
            g_degi[idx] = 0;                     // re-zero for next call
            g_rowstart[idx] = run;
            run += d;
            g_dinv[idx] = (d > 0) ? rsqrtf((float)d) : 0.0f;
            g_cursor[idx] = 0;
        }
    }
    if (t == 255) g_rowstart[NN] = run;
}

__global__ __launch_bounds__(256) void deg_cvt_scan_kernel(
    const void* __restrict__ ei, const float* __restrict__ x,
    const float* __restrict__ wi, const float* __restrict__ wr)
{
    const int bid = blockIdx.x;
    if (bid < DEG_BLOCKS) {
        const int is64 = block_is64((const int*)ei);
        int e = bid * 256 + threadIdx.x;
        if (e < EE) atomicAdd(&g_degi[load_idx2(ei, 1, e, is64)], 1);

        // last-done-block runs the scan
        __shared__ int s_ticket;
        __threadfence();
        __syncthreads();
        if (threadIdx.x == 0) s_ticket = atomicAdd(&g_done, 1);
        __syncthreads();
        if (s_ticket == DEG_BLOCKS - 1) {
            if (threadIdx.x == 0) g_done = 0;    // reset for next call
            __threadfence();
            scan_256();
        }
    } else if (bid < DEG_BLOCKS + CVTX_BLOCKS) {
        const int gi = (bid - DEG_BLOCKS) * 256 + threadIdx.x;
        if (gi < CVTX_GROUPS) {
            const float* p = x + (size_t)gi * 8;
            float4 v0 = *(const float4*)(p);
            float4 v1 = *(const float4*)(p + 4);
            *(uint4*)(g_xh + (size_t)gi * 4) =
                make_uint4(pack_h2(v0.x, v0.y), pack_h2(v0.z, v0.w),
                           pack_h2(v1.x, v1.y), pack_h2(v1.z, v1.w));
        }
    } else {
        // W^T with k-group word permutation {0,4,1,5,2,6,3,7} per 16-k group
        const int ti = (bid - DEG_BLOCKS - CVTX_BLOCKS) * 256 + threadIdx.x;
        if (ti < CVTW_THREADS) {
            const int n = ti & 255;
            const int grp = (ti >> 8) & 15;
            const int mat = ti >> 12;             // 0..3 = phase*2+km
            const int km = mat & 1;
            const float* src = ((mat < 2) ? wi : wr) + (size_t)km * FF * FF;
            float v[16];
#pragma unroll
            for (int j = 0; j < 16; ++j)
                v[j] = src[(size_t)(grp * 16 + j) * FF + n];
            unsigned w[8];
#pragma unroll
            for (int q = 0; q < 8; ++q) w[q] = pack_h2(v[2 * q], v[2 * q + 1]);
            unsigned* o = &g_wh[mat >> 1][km][n][grp * 8];
            *(uint4*)(o)     = make_uint4(w[0], w[4], w[1], w[5]);
            *(uint4*)(o + 4) = make_uint4(w[2], w[6], w[3], w[7]);
        }
    }
}

// ---------------------------------------------------------------------------
// 2) CSR fill
// ---------------------------------------------------------------------------
__global__ __launch_bounds__(256) void fill_csr_kernel(const void* __restrict__ ei) {
    const int is64 = block_is64((const int*)ei);
    int e = blockIdx.x * blockDim.x + threadIdx.x;
    if (e >= EE) return;
    int src = load_idx2(ei, 0, e, is64);
    int dst = load_idx2(ei, 1, e, is64);
    int pos = atomicAdd(&g_cursor[dst], 1);
    int idx = g_rowstart[dst] + pos;
    g_csr_src[idx] = src;
    g_csr_w[idx] = g_dinv[src] * g_dinv[dst];
}

// ---------------------------------------------------------------------------
// 3) gather: xp = A_hat @ x (fp16 in, fp32 accum, fp16 out), warp per node
// ---------------------------------------------------------------------------
__device__ __forceinline__ void acc_u4(float4& a0, float4& a1, uint4 u, float w) {
    float2 p;
    p = h2f2(u.x); a0.x += w * p.x; a0.y += w * p.y;
    p = h2f2(u.y); a0.z += w * p.x; a0.w += w * p.y;
    p = h2f2(u.z); a1.x += w * p.x; a1.y += w * p.y;
    p = h2f2(u.w); a1.z += w * p.x; a1.w += w * p.y;
}

__global__ __launch_bounds__(256) void gather_kernel() {
    const int warp = (blockIdx.x * blockDim.x + threadIdx.x) >> 5;
    const int lane = threadIdx.x & 31;
    if (warp >= NN) return;
    const int n = warp;

    float4 a0 = make_float4(0.f, 0.f, 0.f, 0.f);
    float4 a1 = make_float4(0.f, 0.f, 0.f, 0.f);
    const int beg = g_rowstart[n];
    const int end = g_rowstart[n + 1];
    int e = beg;
    for (; e + 1 < end; e += 2) {
        const int s0 = g_csr_src[e], s1 = g_csr_src[e + 1];
        const float w0 = g_csr_w[e], w1 = g_csr_w[e + 1];
        uint4 u = *(const uint4*)(g_xh + (size_t)s0 * (FF / 2) + lane * 4);
        uint4 v = *(const uint4*)(g_xh + (size_t)s1 * (FF / 2) + lane * 4);
        acc_u4(a0, a1, u, w0);
        acc_u4(a0, a1, v, w1);
    }
    if (e < end) {
        const int s0 = g_csr_src[e];
        const float w0 = g_csr_w[e];
        uint4 u = *(const uint4*)(g_xh + (size_t)s0 * (FF / 2) + lane * 4);
        acc_u4(a0, a1, u, w0);
    }
    *(uint4*)(g_xph + (size_t)n * (FF / 2) + lane * 4) =
        make_uint4(pack_h2(a0.x, a0.y), pack_h2(a0.z, a0.w),
                   pack_h2(a1.x, a1.y), pack_h2(a1.z, a1.w));
}

// ---------------------------------------------------------------------------
// 4) Fused fp16 GEMM + epilogue; cp.async 4-stage, ONE sync per iter.
// Block 128(M) x 128(N), BK=32 halves, 512 threads (4Mx4N warps, 32x32 warp tile).
// (Exact R11/R14 inner loop — best measured configuration.)
// ---------------------------------------------------------------------------
#define AS_STRIDE 20
#define BS_STRIDE 24
#define AS_WORDS (128 * AS_STRIDE)                 // 2560
#define BS_WORDS (2 * 128 * BS_STRIDE)             // 6144
#define STAGE_WORDS (AS_WORDS + BS_WORDS)          // 8704
#define NSTAGES 4
#define GEMM_SMEM (NSTAGES * STAGE_WORDS * 4)      // 139264 B

__device__ __forceinline__ void cp16(unsigned smaddr, const void* gptr, int valid) {
    asm volatile("cp.async.cg.shared.global [%0], [%1], 16, %2;"
                 :: "r"(smaddr), "l"(gptr), "r"(valid ? 16 : 0));
}
__device__ __forceinline__ void cp_commit() {
    asm volatile("cp.async.commit_group;");
}
template <int N>
__device__ __forceinline__ void cp_wait() {
    asm volatile("cp.async.wait_group %0;" :: "n"(N));
}

__device__ __forceinline__ void mma_f16(float* c, const unsigned* a, const unsigned* b) {
    asm volatile(
        "mma.sync.aligned.m16n8k16.row.col.f32.f16.f16.f32 "
        "{%0,%1,%2,%3}, {%4,%5,%6,%7}, {%8,%9}, {%0,%1,%2,%3};\n"
        : "+f"(c[0]), "+f"(c[1]), "+f"(c[2]), "+f"(c[3])
        : "r"(a[0]), "r"(a[1]), "r"(a[2]), "r"(a[3]), "r"(b[0]), "r"(b[1]));
}

__global__ __launch_bounds__(512, 1) void fused_gemm_kernel(
    const float* __restrict__ x, const float* __restrict__ bias,
    float* __restrict__ out)
{
    extern __shared__ unsigned sm[];

    const int tid = threadIdx.x;
    const int lane = tid & 31;
    const int wid = tid >> 5;
    const int warpM = wid & 3;
    const int warpN = wid >> 2;
    const int tileRow = blockIdx.y * 128;
    const int colBase = blockIdx.x * 128;

    auto issue = [&](int it, int st) {
        const int phase = it >> 3;
        const int kw = (it & 7) * 16;                 // word offset within row
        const unsigned* Ah = phase ? g_xh : g_xph;
        unsigned* As = sm + st * STAGE_WORDS;
        unsigned* Bs = As + AS_WORDS;
        unsigned as_base = (unsigned)__cvta_generic_to_shared(As);
        unsigned bs_base = (unsigned)__cvta_generic_to_shared(Bs);
        // A: 128 rows x 16 words -> 1 cp16 per thread
        {
            int m = tid >> 2, c = tid & 3;
            int row = tileRow + m;
            int valid = row < NN;
            int rowc = valid ? row : 0;
            cp16(as_base + (m * AS_STRIDE + c * 4) * 4,
                 Ah + (size_t)rowc * (FF / 2) + kw + c * 4, valid);
        }
        // B: 256 (km,n) rows x 16 words -> 2 cp16 per thread
#pragma unroll
        for (int i = 0; i < 2; ++i) {
            int ii = i * 512 + tid;
            int km = ii >> 9, n = (ii >> 2) & 127, c = ii & 3;
            cp16(bs_base + ((km * 128 + n) * BS_STRIDE + c * 4) * 4,
                 &g_wh[phase][km][colBase + n][kw + c * 4], 1);
        }
        cp_commit();
    };

    float acc[2][2][4][4] = {};   // [km][mt][nt][c]

    issue(0, 0);
    issue(1, 1);
    issue(2, 2);

    for (int it = 0; it < KITERS; ++it) {
        if (it < KITERS - 2)       cp_wait<2>();
        else if (it == KITERS - 2) cp_wait<1>();
        else                       cp_wait<0>();
        __syncthreads();
        if (it + 3 < KITERS) issue(it + 3, (it + 3) % NSTAGES);

        const unsigned* As = sm + (it % NSTAGES) * STAGE_WORDS;
        const unsigned* Bs = As + AS_WORDS;
        const int q = lane & 3;
        const int g = lane >> 2;

#pragma unroll
        for (int ks = 0; ks < 2; ++ks) {              // two k16 steps per BK=32
            const int kb = ks * 8;
            unsigned a[2][4];
#pragma unroll
            for (int mt = 0; mt < 2; ++mt) {
                int mrow = warpM * 32 + mt * 16 + g;
                const unsigned* r0 = As + mrow * AS_STRIDE + kb + q;
                const unsigned* r1 = As + (mrow + 8) * AS_STRIDE + kb + q;
                a[mt][0] = r0[0];
                a[mt][1] = r1[0];
                a[mt][2] = r0[4];
                a[mt][3] = r1[4];
            }
            uint2 b[2][4];
#pragma unroll
            for (int km = 0; km < 2; ++km)
#pragma unroll
                for (int nt = 0; nt < 4; ++nt) {
                    int ncol = warpN * 32 + nt * 8 + g;
                    b[km][nt] = *(const uint2*)(Bs + (km * 128 + ncol) * BS_STRIDE
                                                + kb + 2 * q);
                }
#pragma unroll
            for (int km = 0; km < 2; ++km)
#pragma unroll
                for (int mt = 0; mt < 2; ++mt)
#pragma unroll
                    for (int nt = 0; nt < 4; ++nt)
                        mma_f16(acc[km][mt][nt], a[mt], (const unsigned*)&b[km][nt]);
        }
    }

    // Epilogue: out = x + relu(0.5*(relu(C0+b0)+relu(C1+b1)))
#pragma unroll
    for (int mt = 0; mt < 2; ++mt) {
#pragma unroll
        for (int nt = 0; nt < 4; ++nt) {
            const int col = colBase + warpN * 32 + nt * 8 + 2 * (lane & 3);
            const float bi00 = bias[col],      bi01 = bias[col + 1];
            const float bi10 = bias[FF + col], bi11 = bias[FF + col + 1];
            const int r0 = tileRow + warpM * 32 + mt * 16 + (lane >> 2);

            if (r0 < NN) {
                float2 xv = *(const float2*)(x + (size_t)r0 * FF + col);
                float u0 = fmaxf(acc[0][mt][nt][0] + bi00, 0.f);
                float v0 = fmaxf(acc[1][mt][nt][0] + bi10, 0.f);
                float u1 = fmaxf(acc[0][mt][nt][1] + bi01, 0.f);
                float v1 = fmaxf(acc[1][mt][nt][1] + bi11, 0.f);
                float2 o;
                o.x = xv.x + fmaxf(0.5f * (u0 + v0), 0.f);
                o.y = xv.y + fmaxf(0.5f * (u1 + v1), 0.f);
                *(float2*)(out + (size_t)r0 * FF + col) = o;
            }
            const int r1 = r0 + 8;
            if (r1 < NN) {
                float2 xv = *(const float2*)(x + (size_t)r1 * FF + col);
                float u0 = fmaxf(acc[0][mt][nt][2] + bi00, 0.f);
                float v0 = fmaxf(acc[1][mt][nt][2] + bi10, 0.f);
                float u1 = fmaxf(acc[0][mt][nt][3] + bi01, 0.f);
                float v1 = fmaxf(acc[1][mt][nt][3] + bi11, 0.f);
                float2 o;
                o.x = xv.x + fmaxf(0.5f * (u0 + v0), 0.f);
                o.y = xv.y + fmaxf(0.5f * (u1 + v1), 0.f);
                *(float2*)(out + (size_t)r1 * FF + col) = o;
            }
        }
    }
}

// ---------------------------------------------------------------------------
// launch: 4 kernels (GEMM is #4 -> profiled by ncu)
// ---------------------------------------------------------------------------
extern "C" void kernel_launch(void* const* d_in, const int* in_sizes, int n_in,
                              void* d_out, int out_size) {
    const float* x    = (const float*)d_in[0];
    const void* ei    = d_in[1];
    const float* wi   = (const float*)d_in[2];
    const float* wr   = (const float*)d_in[3];
    const float* bias = (const float*)d_in[4];
    float* out        = (float*)d_out;

    static int smem_set = 0;
    if (!smem_set) {
        cudaFuncSetAttribute(fused_gemm_kernel,
                             cudaFuncAttributeMaxDynamicSharedMemorySize, GEMM_SMEM);
        smem_set = 1;
    }

    deg_cvt_scan_kernel<<<DEG_BLOCKS + CVTX_BLOCKS + CVTW_BLOCKS, 256>>>(
        ei, x, wi, wr);                                                        // 1
    fill_csr_kernel<<<(EE + 255) / 256, 256>>>(ei);                            // 2
    gather_kernel<<<(NN * 32 + 255) / 256, 256>>>();                           // 3
    dim3 ggrid(FF / 128, (NN + 127) / 128);                                    // (2, 391)
    fused_gemm_kernel<<<ggrid, 512, GEMM_SMEM>>>(x, bias, out);                // 4
}

// round 16
// speedup vs baseline: 1.1957x; 1.1957x over previous
#include <cuda_runtime.h>
#include <cuda_fp16.h>
#include <stdint.h>

#define NN 50000
#define EE 320000
#define FF 256
#define KK 2
#define KDIM 512
#define KITERS 16        // KDIM / 32 (BK = 32 halves)

// Scratch (allocation-free rule: __device__ globals). fp16 packed as half2 words.
// g_degi zero at load; scan re-zeroes after reading so graph replays see zeros.
__device__ unsigned g_xph[(size_t)NN * FF / 2];      // half2(A_hat @ x)
__device__ unsigned g_xh[(size_t)NN * FF / 2];       // half2(x)
__device__ unsigned g_wh[2][KK][FF][FF / 2];         // half2 W^T, k-permuted per 8-word group
__device__ int   g_degi[NN];
__device__ float g_dinv[NN];
__device__ int   g_rowstart[NN + 1];
__device__ int   g_cursor[NN];
__device__ int   g_csr_src[EE];
__device__ float g_csr_w[EE];

__device__ __forceinline__ unsigned pack_h2(float a, float b) {
    __half2 h = __floats2half2_rn(a, b);
    return *(unsigned*)&h;
}
__device__ __forceinline__ float2 h2f2(unsigned u) {
    return __half22float2(*(__half2*)&u);
}

// Per-block dtype sniff: int64 edge_index (ids < 2^31) => all odd 32-bit words 0.
__device__ __forceinline__ int block_is64(const int* __restrict__ ei32) {
    __shared__ int s_any;
    if (threadIdx.x == 0) s_any = 0;
    __syncthreads();
    int v = ei32[2 * threadIdx.x + 1];
    v = __reduce_or_sync(0xffffffffu, v);
    if ((threadIdx.x & 31) == 0 && v) atomicOr(&s_any, 1);
    __syncthreads();
    return s_any == 0;
}

__device__ __forceinline__ int load_idx2(const void* ei, int which, int e, int is64) {
    if (is64) return (int)((const long long*)ei)[(size_t)which * EE + e];
    return ((const int*)ei)[(size_t)which * EE + e];
}

// ---------------------------------------------------------------------------
// 1) deg + cvt_x + cvt_w fused (independent work, co-scheduled blocks)
// ---------------------------------------------------------------------------
#define DEG_BLOCKS ((EE + 255) / 256)             // 1250
#define CVTX_GROUPS (NN * FF / 8)                 // 1,600,000
#define CVTX_BLOCKS ((CVTX_GROUPS + 255) / 256)   // 6250
#define CVTW_THREADS (2 * KK * FF * (FF / 16))    // 16384
#define CVTW_BLOCKS (CVTW_THREADS / 256)          // 64

__global__ __launch_bounds__(256) void deg_cvt_kernel(
    const void* __restrict__ ei, const float* __restrict__ x,
    const float* __restrict__ wi, const float* __restrict__ wr)
{
    const int bid = blockIdx.x;
    if (bid < DEG_BLOCKS) {
        const int is64 = block_is64((const int*)ei);
        int e = bid * 256 + threadIdx.x;
        if (e < EE) atomicAdd(&g_degi[load_idx2(ei, 1, e, is64)], 1);
    } else if (bid < DEG_BLOCKS + CVTX_BLOCKS) {
        const int gi = (bid - DEG_BLOCKS) * 256 + threadIdx.x;
        if (gi < CVTX_GROUPS) {
            const float* p = x + (size_t)gi * 8;
            float4 v0 = *(const float4*)(p);
            float4 v1 = *(const float4*)(p + 4);
            *(uint4*)(g_xh + (size_t)gi * 4) =
                make_uint4(pack_h2(v0.x, v0.y), pack_h2(v0.z, v0.w),
                           pack_h2(v1.x, v1.y), pack_h2(v1.z, v1.w));
        }
    } else {
        // W^T with k-group word permutation {0,4,1,5,2,6,3,7} per 16-k group
        const int ti = (bid - DEG_BLOCKS - CVTX_BLOCKS) * 256 + threadIdx.x;
        if (ti < CVTW_THREADS) {
            const int n = ti & 255;
            const int grp = (ti >> 8) & 15;
            const int mat = ti >> 12;             // 0..3 = phase*2+km
            const int km = mat & 1;
            const float* src = ((mat < 2) ? wi : wr) + (size_t)km * FF * FF;
            float v[16];
#pragma unroll
            for (int j = 0; j < 16; ++j)
                v[j] = src[(size_t)(grp * 16 + j) * FF + n];
            unsigned w[8];
#pragma unroll
            for (int q = 0; q < 8; ++q) w[q] = pack_h2(v[2 * q], v[2 * q + 1]);
            unsigned* o = &g_wh[mat >> 1][km][n][grp * 8];
            *(uint4*)(o)     = make_uint4(w[0], w[4], w[1], w[5]);
            *(uint4*)(o + 4) = make_uint4(w[2], w[6], w[3], w[7]);
        }
    }
}

// ---------------------------------------------------------------------------
// 2) scan (+ dinv; zeroes g_degi after reading so the NEXT call sees zeros)
// ---------------------------------------------------------------------------
#define SCAN_CH 49

__global__ __launch_bounds__(1024) void scan_kernel() {
    __shared__ int s[1024];
    const int t = threadIdx.x;
    const int base = t * SCAN_CH;
    int deg[SCAN_CH];
    int sum = 0;
#pragma unroll
    for (int i = 0; i < SCAN_CH; ++i) {
        int idx = base + i;
        deg[i] = 0;
        if (idx < NN) {
            deg[i] = g_degi[idx];
            g_degi[idx] = 0;                       // re-zero for next call
            sum += deg[i];
            g_dinv[idx] = (deg[i] > 0) ? rsqrtf((float)deg[i]) : 0.0f;
        }
    }
    s[t] = sum;
    __syncthreads();
    for (int off = 1; off < 1024; off <<= 1) {
        int v = (t >= off) ? s[t - off] : 0;
        __syncthreads();
        s[t] += v;
        __syncthreads();
    }
    int run = (t == 0) ? 0 : s[t - 1];
#pragma unroll
    for (int i = 0; i < SCAN_CH; ++i) {
        int idx = base + i;
        if (idx < NN) {
            g_rowstart[idx] = run;
            run += deg[i];
            g_cursor[idx] = 0;
        }
    }
    if (t == 1023) g_rowstart[NN] = run;
}

// ---------------------------------------------------------------------------
// 3) CSR fill
// ---------------------------------------------------------------------------
__global__ __launch_bounds__(256) void fill_csr_kernel(const void* __restrict__ ei) {
    const int is64 = block_is64((const int*)ei);
    int e = blockIdx.x * blockDim.x + threadIdx.x;
    if (e >= EE) return;
    int src = load_idx2(ei, 0, e, is64);
    int dst = load_idx2(ei, 1, e, is64);
    int pos = atomicAdd(&g_cursor[dst], 1);
    int idx = g_rowstart[dst] + pos;
    g_csr_src[idx] = src;
    g_csr_w[idx] = g_dinv[src] * g_dinv[dst];
}

// ---------------------------------------------------------------------------
// 4) gather: xp = A_hat @ x (fp16 in, fp32 accum, fp16 out), warp per node
// ---------------------------------------------------------------------------
__device__ __forceinline__ void acc_u4(float4& a0, float4& a1, uint4 u, float w) {
    float2 p;
    p = h2f2(u.x); a0.x += w * p.x; a0.y += w * p.y;
    p = h2f2(u.y); a0.z += w * p.x; a0.w += w * p.y;
    p = h2f2(u.z); a1.x += w * p.x; a1.y += w * p.y;
    p = h2f2(u.w); a1.z += w * p.x; a1.w += w * p.y;
}

__global__ __launch_bounds__(256) void gather_kernel() {
    const int warp = (blockIdx.x * blockDim.x + threadIdx.x) >> 5;
    const int lane = threadIdx.x & 31;
    if (warp >= NN) return;
    const int n = warp;

    float4 a0 = make_float4(0.f, 0.f, 0.f, 0.f);
    float4 a1 = make_float4(0.f, 0.f, 0.f, 0.f);
    const int beg = g_rowstart[n];
    const int end = g_rowstart[n + 1];
    int e = beg;
    for (; e + 1 < end; e += 2) {
        const int s0 = g_csr_src[e], s1 = g_csr_src[e + 1];
        const float w0 = g_csr_w[e], w1 = g_csr_w[e + 1];
        uint4 u = *(const uint4*)(g_xh + (size_t)s0 * (FF / 2) + lane * 4);
        uint4 v = *(const uint4*)(g_xh + (size_t)s1 * (FF / 2) + lane * 4);
        acc_u4(a0, a1, u, w0);
        acc_u4(a0, a1, v, w1);
    }
    if (e < end) {
        const int s0 = g_csr_src[e];
        const float w0 = g_csr_w[e];
        uint4 u = *(const uint4*)(g_xh + (size_t)s0 * (FF / 2) + lane * 4);
        acc_u4(a0, a1, u, w0);
    }
    *(uint4*)(g_xph + (size_t)n * (FF / 2) + lane * 4) =
        make_uint4(pack_h2(a0.x, a0.y), pack_h2(a0.z, a0.w),
                   pack_h2(a1.x, a1.y), pack_h2(a1.z, a1.w));
}

// ---------------------------------------------------------------------------
// 5) Fused fp16 GEMM + epilogue — OCCUPANCY build.
// Block 64(M) x 64(N) x 2km, BK=32 halves, 256 threads (2Mx4N warps,
// warp tile 32Mx16N per km). 3 cp.async stages, one sync per iter.
// smem 52 KB, ~80 regs -> 3 CTAs/SM (24 warps).
// ---------------------------------------------------------------------------
#define AS_STRIDE 20
#define BS_STRIDE 24
#define AS_WORDS (64 * AS_STRIDE)                  // 1280
#define BS_WORDS (2 * 64 * BS_STRIDE)              // 3072
#define STAGE_WORDS (AS_WORDS + BS_WORDS)          // 4352
#define NSTAGES 3
#define GEMM_SMEM (NSTAGES * STAGE_WORDS * 4)      // 52224 B

__device__ __forceinline__ void cp16(unsigned smaddr, const void* gptr, int valid) {
    asm volatile("cp.async.cg.shared.global [%0], [%1], 16, %2;"
                 :: "r"(smaddr), "l"(gptr), "r"(valid ? 16 : 0));
}
__device__ __forceinline__ void cp_commit() {
    asm volatile("cp.async.commit_group;");
}
template <int N>
__device__ __forceinline__ void cp_wait() {
    asm volatile("cp.async.wait_group %0;" :: "n"(N));
}

__device__ __forceinline__ void mma_f16(float* c, const unsigned* a, const unsigned* b) {
    asm volatile(
        "mma.sync.aligned.m16n8k16.row.col.f32.f16.f16.f32 "
        "{%0,%1,%2,%3}, {%4,%5,%6,%7}, {%8,%9}, {%0,%1,%2,%3};\n"
        : "+f"(c[0]), "+f"(c[1]), "+f"(c[2]), "+f"(c[3])
        : "r"(a[0]), "r"(a[1]), "r"(a[2]), "r"(a[3]), "r"(b[0]), "r"(b[1]));
}

__global__ __launch_bounds__(256, 3) void fused_gemm_kernel(
    const float* __restrict__ x, const float* __restrict__ bias,
    float* __restrict__ out)
{
    extern __shared__ unsigned sm[];

    const int tid = threadIdx.x;
    const int lane = tid & 31;
    const int wid = tid >> 5;
    const int warpM = wid & 1;                     // 2 warps over M (32 rows each)
    const int warpN = wid >> 1;                    // 4 warps over N (16 cols each)
    const int tileRow = blockIdx.y * 64;
    const int colBase = blockIdx.x * 64;

    auto issue = [&](int it, int st) {
        const int phase = it >> 3;
        const int kw = (it & 7) * 16;              // word offset within row
        const unsigned* Ah = phase ? g_xh : g_xph;
        unsigned* As = sm + st * STAGE_WORDS;
        unsigned* Bs = As + AS_WORDS;
        unsigned as_base = (unsigned)__cvta_generic_to_shared(As);
        unsigned bs_base = (unsigned)__cvta_generic_to_shared(Bs);
        // A: 64 rows x 16 words -> 1 cp16 per thread
        {
            int m = tid >> 2, c = tid & 3;
            int row = tileRow + m;
            int valid = row < NN;
            int rowc = valid ? row : 0;
            cp16(as_base + (m * AS_STRIDE + c * 4) * 4,
                 Ah + (size_t)rowc * (FF / 2) + kw + c * 4, valid);
        }
        // B: 128 (km,n) rows x 16 words -> 2 cp16 per thread
#pragma unroll
        for (int i = 0; i < 2; ++i) {
            int ii = i * 256 + tid;
            int km = ii >> 8, n = (ii >> 2) & 63, c = ii & 3;
            cp16(bs_base + ((km * 64 + n) * BS_STRIDE + c * 4) * 4,
                 &g_wh[phase][km][colBase + n][kw + c * 4], 1);
        }
        cp_commit();
    };

    float acc[2][2][2][4] = {};   // [km][mt][nt][c]

    issue(0, 0);
    issue(1, 1);

    for (int it = 0; it < KITERS; ++it) {
        if (it < KITERS - 1) cp_wait<1>();
        else                 cp_wait<0>();
        __syncthreads();
        if (it + 2 < KITERS) issue(it + 2, (it + 2) % NSTAGES);

        const unsigned* As = sm + (it % NSTAGES) * STAGE_WORDS;
        const unsigned* Bs = As + AS_WORDS;
        const int q = lane & 3;
        const int g = lane >> 2;

#pragma unroll
        for (int ks = 0; ks < 2; ++ks) {           // two k16 steps per BK=32
            const int kb = ks * 8;
            unsigned a[2][4];
#pragma unroll
            for (int mt = 0; mt < 2; ++mt) {
                int mrow = warpM * 32 + mt * 16 + g;
                const unsigned* r0 = As + mrow * AS_STRIDE + kb + q;
                const unsigned* r1 = As + (mrow + 8) * AS_STRIDE + kb + q;
                a[mt][0] = r0[0];
                a[mt][1] = r1[0];
                a[mt][2] = r0[4];
                a[mt][3] = r1[4];
            }
            uint2 b[2][2];
#pragma unroll
            for (int km = 0; km < 2; ++km)
#pragma unroll
                for (int nt = 0; nt < 2; ++nt) {
                    int ncol = warpN * 16 + nt * 8 + g;
                    b[km][nt] = *(const uint2*)(Bs + (km * 64 + ncol) * BS_STRIDE
                                                + kb + 2 * q);
                }
#pragma unroll
            for (int km = 0; km < 2; ++km)
#pragma unroll
                for (int mt = 0; mt < 2; ++mt)
#pragma unroll
                    for (int nt = 0; nt < 2; ++nt)
                        mma_f16(acc[km][mt][nt], a[mt], (const unsigned*)&b[km][nt]);
        }
    }

    // Epilogue: out = x + relu(0.5*(relu(C0+b0)+relu(C1+b1)))
#pragma unroll
    for (int mt = 0; mt < 2; ++mt) {
#pragma unroll
        for (int nt = 0; nt < 2; ++nt) {
            const int col = colBase + warpN * 16 + nt * 8 + 2 * (lane & 3);
            const float bi00 = bias[col],      bi01 = bias[col + 1];
            const float bi10 = bias[FF + col], bi11 = bias[FF + col + 1];
            const int r0 = tileRow + warpM * 32 + mt * 16 + (lane >> 2);

            if (r0 < NN) {
                float2 xv = *(const float2*)(x + (size_t)r0 * FF + col);
                float u0 = fmaxf(acc[0][mt][nt][0] + bi00, 0.f);
                float v0 = fmaxf(acc[1][mt][nt][0] + bi10, 0.f);
                float u1 = fmaxf(acc[0][mt][nt][1] + bi01, 0.f);
                float v1 = fmaxf(acc[1][mt][nt][1] + bi11, 0.f);
                float2 o;
                o.x = xv.x + fmaxf(0.5f * (u0 + v0), 0.f);
                o.y = xv.y + fmaxf(0.5f * (u1 + v1), 0.f);
                *(float2*)(out + (size_t)r0 * FF + col) = o;
            }
            const int r1 = r0 + 8;
            if (r1 < NN) {
                float2 xv = *(const float2*)(x + (size_t)r1 * FF + col);
                float u0 = fmaxf(acc[0][mt][nt][2] + bi00, 0.f);
                float v0 = fmaxf(acc[1][mt][nt][2] + bi10, 0.f);
                float u1 = fmaxf(acc[0][mt][nt][3] + bi01, 0.f);
                float v1 = fmaxf(acc[1][mt][nt][3] + bi11, 0.f);
                float2 o;
                o.x = xv.x + fmaxf(0.5f * (u0 + v0), 0.f);
                o.y = xv.y + fmaxf(0.5f * (u1 + v1), 0.f);
                *(float2*)(out + (size_t)r1 * FF + col) = o;
            }
        }
    }
}

// ---------------------------------------------------------------------------
// launch: 5 kernels
// ---------------------------------------------------------------------------
extern "C" void kernel_launch(void* const* d_in, const int* in_sizes, int n_in,
                              void* d_out, int out_size) {
    const float* x    = (const float*)d_in[0];
    const void* ei    = d_in[1];
    const float* wi   = (const float*)d_in[2];
    const float* wr   = (const float*)d_in[3];
    const float* bias = (const float*)d_in[4];
    float* out        = (float*)d_out;

    static int smem_set = 0;
    if (!smem_set) {
        cudaFuncSetAttribute(fused_gemm_kernel,
                             cudaFuncAttributeMaxDynamicSharedMemorySize, GEMM_SMEM);
        smem_set = 1;
    }

    deg_cvt_kernel<<<DEG_BLOCKS + CVTX_BLOCKS + CVTW_BLOCKS, 256>>>(
        ei, x, wi, wr);                                                        // 1
    scan_kernel<<<1, 1024>>>();                                                // 2
    fill_csr_kernel<<<(EE + 255) / 256, 256>>>(ei);                            // 3
    gather_kernel<<<(NN * 32 + 255) / 256, 256>>>();                           // 4
    dim3 ggrid(FF / 64, (NN + 63) / 64);                                       // (4, 782)
    fused_gemm_kernel<<<ggrid, 256, GEMM_SMEM>>>(x, bias, out);                // 5
}

// round 17
// speedup vs baseline: 1.9525x; 1.6329x over previous
#include <cuda_runtime.h>
#include <cuda_fp16.h>
#include <stdint.h>

#define NN 50000
#define EE 320000
#define FF 256
#define KK 2
#define KDIM 512
#define KITERS 16        // KDIM / 32 (BK = 32 halves)

// Scratch (allocation-free rule: __device__ globals). fp16 packed as half2 words.
// g_degi zero at load; scanD re-zeroes after reading so graph replays see zeros.
__device__ unsigned g_xph[(size_t)NN * FF / 2];      // half2(A_hat @ x)
__device__ unsigned g_xh[(size_t)NN * FF / 2];       // half2(x)
__device__ unsigned g_wh[2][KK][FF][FF / 2];         // half2 W^T, k-permuted per 8-word group
__device__ int   g_degi[NN];
__device__ float g_dinv[NN];
__device__ int   g_rowstart[NN + 1];
__device__ int   g_cursor[NN];
__device__ int   g_csr_src[EE];
__device__ float g_csr_w[EE];
__device__ int   g_blocksum[196];

__device__ __forceinline__ unsigned pack_h2(float a, float b) {
    __half2 h = __floats2half2_rn(a, b);
    return *(unsigned*)&h;
}
__device__ __forceinline__ float2 h2f2(unsigned u) {
    return __half22float2(*(__half2*)&u);
}

// Per-block dtype sniff: int64 edge_index (ids < 2^31) => all odd 32-bit words 0.
__device__ __forceinline__ int block_is64(const int* __restrict__ ei32) {
    __shared__ int s_any;
    if (threadIdx.x == 0) s_any = 0;
    __syncthreads();
    int v = ei32[2 * threadIdx.x + 1];
    v = __reduce_or_sync(0xffffffffu, v);
    if ((threadIdx.x & 31) == 0 && v) atomicOr(&s_any, 1);
    __syncthreads();
    return s_any == 0;
}

__device__ __forceinline__ int load_idx2(const void* ei, int which, int e, int is64) {
    if (is64) return (int)((const long long*)ei)[(size_t)which * EE + e];
    return ((const int*)ei)[(size_t)which * EE + e];
}

// ---------------------------------------------------------------------------
// 1) deg + cvt_x + cvt_w fused (independent work, co-scheduled blocks)
// ---------------------------------------------------------------------------
#define DEG_BLOCKS ((EE + 255) / 256)             // 1250
#define CVTX_GROUPS (NN * FF / 8)                 // 1,600,000
#define CVTX_BLOCKS ((CVTX_GROUPS + 255) / 256)   // 6250
#define CVTW_THREADS (2 * KK * FF * (FF / 16))    // 16384
#define CVTW_BLOCKS (CVTW_THREADS / 256)          // 64

__global__ __launch_bounds__(256) void deg_cvt_kernel(
    const void* __restrict__ ei, const float* __restrict__ x,
    const float* __restrict__ wi, const float* __restrict__ wr)
{
    const int bid = blockIdx.x;
    if (bid < DEG_BLOCKS) {
        const int is64 = block_is64((const int*)ei);
        int e = bid * 256 + threadIdx.x;
        if (e < EE) atomicAdd(&g_degi[load_idx2(ei, 1, e, is64)], 1);
    } else if (bid < DEG_BLOCKS + CVTX_BLOCKS) {
        const int gi = (bid - DEG_BLOCKS) * 256 + threadIdx.x;
        if (gi < CVTX_GROUPS) {
            const float* p = x + (size_t)gi * 8;
            float4 v0 = *(const float4*)(p);
            float4 v1 = *(const float4*)(p + 4);
            *(uint4*)(g_xh + (size_t)gi * 4) =
                make_uint4(pack_h2(v0.x, v0.y), pack_h2(v0.z, v0.w),
                           pack_h2(v1.x, v1.y), pack_h2(v1.z, v1.w));
        }
    } else {
        // W^T with k-group word permutation {0,4,1,5,2,6,3,7} per 16-k group
        const int ti = (bid - DEG_BLOCKS - CVTX_BLOCKS) * 256 + threadIdx.x;
        if (ti < CVTW_THREADS) {
            const int n = ti & 255;
            const int grp = (ti >> 8) & 15;
            const int mat = ti >> 12;             // 0..3 = phase*2+km
            const int km = mat & 1;
            const float* src = ((mat < 2) ? wi : wr) + (size_t)km * FF * FF;
            float v[16];
#pragma unroll
            for (int j = 0; j < 16; ++j)
                v[j] = src[(size_t)(grp * 16 + j) * FF + n];
            unsigned w[8];
#pragma unroll
            for (int q = 0; q < 8; ++q) w[q] = pack_h2(v[2 * q], v[2 * q + 1]);
            unsigned* o = &g_wh[mat >> 1][km][n][grp * 8];
            *(uint4*)(o)     = make_uint4(w[0], w[4], w[1], w[5]);
            *(uint4*)(o + 4) = make_uint4(w[2], w[6], w[3], w[7]);
        }
    }
}

// ---------------------------------------------------------------------------
// 2) scanB: dinv + per-block degree sums (196 blocks x 256)
// ---------------------------------------------------------------------------
__global__ __launch_bounds__(256) void scanB_kernel() {
    const int t = threadIdx.x;
    const int idx = blockIdx.x * 256 + t;
    int d = (idx < NN) ? g_degi[idx] : 0;
    if (idx < NN) g_dinv[idx] = (d > 0) ? rsqrtf((float)d) : 0.0f;
    __shared__ int sw[8];
    int s = d;
#pragma unroll
    for (int o = 16; o; o >>= 1) s += __shfl_down_sync(0xffffffffu, s, o);
    if ((t & 31) == 0) sw[t >> 5] = s;
    __syncthreads();
    if (t < 8) {
        int u = sw[t];
#pragma unroll
        for (int o = 4; o; o >>= 1) u += __shfl_down_sync(0xffu, u, o);
        if (t == 0) g_blocksum[blockIdx.x] = u;
    }
}

// ---------------------------------------------------------------------------
// 3) scanD: per-block offset from blocksums + local scan -> rowstart;
//           zeroes g_degi (for replays) and g_cursor.
// ---------------------------------------------------------------------------
__global__ __launch_bounds__(256) void scanD_kernel() {
    const int t = threadIdx.x;
    const int bid = blockIdx.x;
    const int idx = bid * 256 + t;

    // offset = sum of blocksum[0..bid)
    __shared__ int sw[8];
    __shared__ int s_off;
    int v = (t < bid) ? g_blocksum[t] : 0;        // bid <= 195 < 256
    int s = v;
#pragma unroll
    for (int o = 16; o; o >>= 1) s += __shfl_down_sync(0xffffffffu, s, o);
    if ((t & 31) == 0) sw[t >> 5] = s;
    __syncthreads();
    if (t < 8) {
        int u = sw[t];
#pragma unroll
        for (int o = 4; o; o >>= 1) u += __shfl_down_sync(0xffu, u, o);
        if (t == 0) s_off = u;
    }
    __syncthreads();
    const int offset = s_off;

    int d = (idx < NN) ? g_degi[idx] : 0;
    __shared__ int sc[256];
    sc[t] = d;
    __syncthreads();
    for (int o = 1; o < 256; o <<= 1) {
        int x = (t >= o) ? sc[t - o] : 0;
        __syncthreads();
        sc[t] += x;
        __syncthreads();
    }
    int excl = sc[t] - d;
    if (idx < NN) {
        g_rowstart[idx] = offset + excl;
        g_degi[idx] = 0;                           // re-zero for next call
        g_cursor[idx] = 0;
    }
    if (bid == 195 && t == 255) g_rowstart[NN] = offset + sc[255];
}

// ---------------------------------------------------------------------------
// 4) CSR fill
// ---------------------------------------------------------------------------
__global__ __launch_bounds__(256) void fill_csr_kernel(const void* __restrict__ ei) {
    const int is64 = block_is64((const int*)ei);
    int e = blockIdx.x * blockDim.x + threadIdx.x;
    if (e >= EE) return;
    int src = load_idx2(ei, 0, e, is64);
    int dst = load_idx2(ei, 1, e, is64);
    int pos = atomicAdd(&g_cursor[dst], 1);
    int idx = g_rowstart[dst] + pos;
    g_csr_src[idx] = src;
    g_csr_w[idx] = g_dinv[src] * g_dinv[dst];
}

// ---------------------------------------------------------------------------
// 5) gather: xp = A_hat @ x (fp16 in, fp32 accum, fp16 out), warp per node
// ---------------------------------------------------------------------------
__device__ __forceinline__ void acc_u4(float4& a0, float4& a1, uint4 u, float w) {
    float2 p;
    p = h2f2(u.x); a0.x += w * p.x; a0.y += w * p.y;
    p = h2f2(u.y); a0.z += w * p.x; a0.w += w * p.y;
    p = h2f2(u.z); a1.x += w * p.x; a1.y += w * p.y;
    p = h2f2(u.w); a1.z += w * p.x; a1.w += w * p.y;
}

__global__ __launch_bounds__(256) void gather_kernel() {
    const int warp = (blockIdx.x * blockDim.x + threadIdx.x) >> 5;
    const int lane = threadIdx.x & 31;
    if (warp >= NN) return;
    const int n = warp;

    float4 a0 = make_float4(0.f, 0.f, 0.f, 0.f);
    float4 a1 = make_float4(0.f, 0.f, 0.f, 0.f);
    const int beg = g_rowstart[n];
    const int end = g_rowstart[n + 1];
    int e = beg;
    for (; e + 1 < end; e += 2) {
        const int s0 = g_csr_src[e], s1 = g_csr_src[e + 1];
        const float w0 = g_csr_w[e], w1 = g_csr_w[e + 1];
        uint4 u = *(const uint4*)(g_xh + (size_t)s0 * (FF / 2) + lane * 4);
        uint4 v = *(const uint4*)(g_xh + (size_t)s1 * (FF / 2) + lane * 4);
        acc_u4(a0, a1, u, w0);
        acc_u4(a0, a1, v, w1);
    }
    if (e < end) {
        const int s0 = g_csr_src[e];
        const float w0 = g_csr_w[e];
        uint4 u = *(const uint4*)(g_xh + (size_t)s0 * (FF / 2) + lane * 4);
        acc_u4(a0, a1, u, w0);
    }
    *(uint4*)(g_xph + (size_t)n * (FF / 2) + lane * 4) =
        make_uint4(pack_h2(a0.x, a0.y), pack_h2(a0.z, a0.w),
                   pack_h2(a1.x, a1.y), pack_h2(a1.z, a1.w));
}

// ---------------------------------------------------------------------------
// 6) Fused fp16 GEMM + epilogue — occupancy 3 CTA/SM AND pipeline depth 3.
// Block 64(M) x 64(N) x 2km, BK=32 halves, 256 threads (2Mx4N warps).
// 4 cp.async stages x 17.4 KB = 69.6 KB; 3 CTAs/SM = 208.9 KB.
// ---------------------------------------------------------------------------
#define AS_STRIDE 20
#define BS_STRIDE 24
#define AS_WORDS (64 * AS_STRIDE)                  // 1280
#define BS_WORDS (2 * 64 * BS_STRIDE)              // 3072
#define STAGE_WORDS (AS_WORDS + BS_WORDS)          // 4352
#define NSTAGES 4
#define GEMM_SMEM (NSTAGES * STAGE_WORDS * 4)      // 69632 B

__device__ __forceinline__ void cp16(unsigned smaddr, const void* gptr, int valid) {
    asm volatile("cp.async.cg.shared.global [%0], [%1], 16, %2;"
                 :: "r"(smaddr), "l"(gptr), "r"(valid ? 16 : 0));
}
__device__ __forceinline__ void cp_commit() {
    asm volatile("cp.async.commit_group;");
}
template <int N>
__device__ __forceinline__ void cp_wait() {
    asm volatile("cp.async.wait_group %0;" :: "n"(N));
}

__device__ __forceinline__ void mma_f16(float* c, const unsigned* a, const unsigned* b) {
    asm volatile(
        "mma.sync.aligned.m16n8k16.row.col.f32.f16.f16.f32 "
        "{%0,%1,%2,%3}, {%4,%5,%6,%7}, {%8,%9}, {%0,%1,%2,%3};\n"
        : "+f"(c[0]), "+f"(c[1]), "+f"(c[2]), "+f"(c[3])
        : "r"(a[0]), "r"(a[1]), "r"(a[2]), "r"(a[3]), "r"(b[0]), "r"(b[1]));
}

__global__ __launch_bounds__(256, 3) void fused_gemm_kernel(
    const float* __restrict__ x, const float* __restrict__ bias,
    float* __restrict__ out)
{
    extern __shared__ unsigned sm[];

    const int tid = threadIdx.x;
    const int lane = tid & 31;
    const int wid = tid >> 5;
    const int warpM = wid & 1;                     // 2 warps over M (32 rows each)
    const int warpN = wid >> 1;                    // 4 warps over N (16 cols each)
    const int tileRow = blockIdx.y * 64;
    const int colBase = blockIdx.x * 64;

    auto issue = [&](int it, int st) {
        const int phase = it >> 3;
        const int kw = (it & 7) * 16;              // word offset within row
        const unsigned* Ah = phase ? g_xh : g_xph;
        unsigned* As = sm + st * STAGE_WORDS;
        unsigned* Bs = As + AS_WORDS;
        unsigned as_base = (unsigned)__cvta_generic_to_shared(As);
        unsigned bs_base = (unsigned)__cvta_generic_to_shared(Bs);
        // A: 64 rows x 16 words -> 1 cp16 per thread
        {
            int m = tid >> 2, c = tid & 3;
            int row = tileRow + m;
            int valid = row < NN;
            int rowc = valid ? row : 0;
            cp16(as_base + (m * AS_STRIDE + c * 4) * 4,
                 Ah + (size_t)rowc * (FF / 2) + kw + c * 4, valid);
        }
        // B: 128 (km,n) rows x 16 words -> 2 cp16 per thread
#pragma unroll
        for (int i = 0; i < 2; ++i) {
            int ii = i * 256 + tid;
            int km = ii >> 8, n = (ii >> 2) & 63, c = ii & 3;
            cp16(bs_base + ((km * 64 + n) * BS_STRIDE + c * 4) * 4,
                 &g_wh[phase][km][colBase + n][kw + c * 4], 1);
        }
        cp_commit();
    };

    float acc[2][2][2][4] = {};   // [km][mt][nt][c]

    issue(0, 0);
    issue(1, 1);
    issue(2, 2);

    for (int it = 0; it < KITERS; ++it) {
        if (it < KITERS - 2)       cp_wait<2>();
        else if (it == KITERS - 2) cp_wait<1>();
        else                       cp_wait<0>();
        __syncthreads();
        if (it + 3 < KITERS) issue(it + 3, (it + 3) % NSTAGES);

        const unsigned* As = sm + (it % NSTAGES) * STAGE_WORDS;
        const unsigned* Bs = As + AS_WORDS;
        const int q = lane & 3;
        const int g = lane >> 2;

#pragma unroll
        for (int ks = 0; ks < 2; ++ks) {           // two k16 steps per BK=32
            const int kb = ks * 8;
            unsigned a[2][4];
#pragma unroll
            for (int mt = 0; mt < 2; ++mt) {
                int mrow = warpM * 32 + mt * 16 + g;
                const unsigned* r0 = As + mrow * AS_STRIDE + kb + q;
                const unsigned* r1 = As + (mrow + 8) * AS_STRIDE + kb + q;
                a[mt][0] = r0[0];
                a[mt][1] = r1[0];
                a[mt][2] = r0[4];
                a[mt][3] = r1[4];
            }
            uint2 b[2][2];
#pragma unroll
            for (int km = 0; km < 2; ++km)
#pragma unroll
                for (int nt = 0; nt < 2; ++nt) {
                    int ncol = warpN * 16 + nt * 8 + g;
                    b[km][nt] = *(const uint2*)(Bs + (km * 64 + ncol) * BS_STRIDE
                                                + kb + 2 * q);
                }
#pragma unroll
            for (int km = 0; km < 2; ++km)
#pragma unroll
                for (int mt = 0; mt < 2; ++mt)
#pragma unroll
                    for (int nt = 0; nt < 2; ++nt)
                        mma_f16(acc[km][mt][nt], a[mt], (const unsigned*)&b[km][nt]);
        }
    }

    // Epilogue: out = x + relu(0.5*(relu(C0+b0)+relu(C1+b1)))
#pragma unroll
    for (int mt = 0; mt < 2; ++mt) {
#pragma unroll
        for (int nt = 0; nt < 2; ++nt) {
            const int col = colBase + warpN * 16 + nt * 8 + 2 * (lane & 3);
            const float bi00 = bias[col],      bi01 = bias[col + 1];
            const float bi10 = bias[FF + col], bi11 = bias[FF + col + 1];
            const int r0 = tileRow + warpM * 32 + mt * 16 + (lane >> 2);

            if (r0 < NN) {
                float2 xv = *(const float2*)(x + (size_t)r0 * FF + col);
                float u0 = fmaxf(acc[0][mt][nt][0] + bi00, 0.f);
                float v0 = fmaxf(acc[1][mt][nt][0] + bi10, 0.f);
                float u1 = fmaxf(acc[0][mt][nt][1] + bi01, 0.f);
                float v1 = fmaxf(acc[1][mt][nt][1] + bi11, 0.f);
                float2 o;
                o.x = xv.x + fmaxf(0.5f * (u0 + v0), 0.f);
                o.y = xv.y + fmaxf(0.5f * (u1 + v1), 0.f);
                *(float2*)(out + (size_t)r0 * FF + col) = o;
            }
            const int r1 = r0 + 8;
            if (r1 < NN) {
                float2 xv = *(const float2*)(x + (size_t)r1 * FF + col);
                float u0 = fmaxf(acc[0][mt][nt][2] + bi00, 0.f);
                float v0 = fmaxf(acc[1][mt][nt][2] + bi10, 0.f);
                float u1 = fmaxf(acc[0][mt][nt][3] + bi01, 0.f);
                float v1 = fmaxf(acc[1][mt][nt][3] + bi11, 0.f);
                float2 o;
                o.x = xv.x + fmaxf(0.5f * (u0 + v0), 0.f);
                o.y = xv.y + fmaxf(0.5f * (u1 + v1), 0.f);
                *(float2*)(out + (size_t)r1 * FF + col) = o;
            }
        }
    }
}

// ---------------------------------------------------------------------------
// launch: 6 kernels
// ---------------------------------------------------------------------------
extern "C" void kernel_launch(void* const* d_in, const int* in_sizes, int n_in,
                              void* d_out, int out_size) {
    const float* x    = (const float*)d_in[0];
    const void* ei    = d_in[1];
    const float* wi   = (const float*)d_in[2];
    const float* wr   = (const float*)d_in[3];
    const float* bias = (const float*)d_in[4];
    float* out        = (float*)d_out;

    static int smem_set = 0;
    if (!smem_set) {
        cudaFuncSetAttribute(fused_gemm_kernel,
                             cudaFuncAttributeMaxDynamicSharedMemorySize, GEMM_SMEM);
        smem_set = 1;
    }

    deg_cvt_kernel<<<DEG_BLOCKS + CVTX_BLOCKS + CVTW_BLOCKS, 256>>>(
        ei, x, wi, wr);                                                        // 1
    scanB_kernel<<<196, 256>>>();                                              // 2
    scanD_kernel<<<196, 256>>>();                                              // 3
    fill_csr_kernel<<<(EE + 255) / 256, 256>>>(ei);                            // 4
    gather_kernel<<<(NN * 32 + 255) / 256, 256>>>();                           // 5
    dim3 ggrid(FF / 64, (NN + 63) / 64);                                       // (4, 782)
    fused_gemm_kernel<<<ggrid, 256, GEMM_SMEM>>>(x, bias, out);                // 6
}